// round 4
// baseline (speedup 1.0000x reference)
#include <cuda_runtime.h>
#include <cstdint>

#define D 64
#define MAXN 100000
#define MAXE 1600000
#define WAVE 128
#define NT 256

#define ENT 256
#define ENW 8
#define RING 8          // ring slots (power of 2)
#define LAD 6           // prefetch distance; MUST be < RING
#define LWS 68          // padded row stride for sLW

// Scratch (static device globals; no runtime allocation allowed)
__device__ float g_h[(size_t)MAXN * D];   // h = node_h @ W_fc^T
__device__ int   g_deg[MAXN];
__device__ int   g_off[MAXN + 1];
__device__ int   g_cur[MAXN];
__device__ int2  g_pes[MAXE];             // permuted (edge_idx, src)

typedef unsigned long long ull;

__device__ __forceinline__ ull fma2(ull a, ull b, ull c) {
    ull d;
    asm("fma.rn.f32x2 %0, %1, %2, %3;" : "=l"(d) : "l"(a), "l"(b), "l"(c));
    return d;
}
__device__ __forceinline__ float2 unpack2(ull v) {
    float2 r;
    asm("mov.b64 {%0, %1}, %2;" : "=f"(r.x), "=f"(r.y) : "l"(v));
    return r;
}
__device__ __forceinline__ void cp16(void* s, const void* g) {
    unsigned a = (unsigned)__cvta_generic_to_shared(s);
    asm volatile("cp.async.cg.shared.global [%0], [%1], 16;" :: "r"(a), "l"(g));
}
__device__ __forceinline__ void cp8(void* s, const void* g) {
    unsigned a = (unsigned)__cvta_generic_to_shared(s);
    asm volatile("cp.async.ca.shared.global [%0], [%1], 8;" :: "r"(a), "l"(g));
}
#define CP_COMMIT() asm volatile("cp.async.commit_group;" ::: "memory")
#define CP_WAIT1()  asm volatile("cp.async.wait_group 1;" ::: "memory")
#define CP_WAIT0()  asm volatile("cp.async.wait_group 0;" ::: "memory")
#define CP_WAITLAD() asm volatile("cp.async.wait_group 6;" ::: "memory")  // == LAD

// ---------------------------------------------------------------------------
__global__ void k_zero(int n4) {  // zero g_deg; n4 = ceil(N/4)
    int i = blockIdx.x * blockDim.x + threadIdx.x;
    if (i < n4) ((int4*)g_deg)[i] = make_int4(0, 0, 0, 0);
}

__global__ void k_hist(const int* __restrict__ dst, int E) {
    int i = blockIdx.x * blockDim.x + threadIdx.x;
    if (i < E) atomicAdd(&g_deg[dst[i]], 1);
}

// single block, 1024 threads: exclusive scan of g_deg -> g_off (and g_cur copy)
__global__ void k_scan(int N, int E) {
    __shared__ int s[1024];
    int t = threadIdx.x;
    int chunk = (N + 1023) >> 10;
    int lo = t * chunk;
    int hi = lo + chunk; if (hi > N) hi = N;
    int sum = 0;
    for (int i = lo; i < hi; i++) sum += g_deg[i];
    s[t] = sum; __syncthreads();
    for (int d = 1; d < 1024; d <<= 1) {
        int v = (t >= d) ? s[t - d] : 0;
        __syncthreads();
        s[t] += v;
        __syncthreads();
    }
    int run = (t == 0) ? 0 : s[t - 1];
    for (int i = lo; i < hi; i++) {
        int dg = g_deg[i];
        g_off[i] = run; g_cur[i] = run;
        run += dg;
    }
    if (hi == N) g_off[N] = run;
}

__global__ void k_scatter(const int* __restrict__ src, const int* __restrict__ dst, int E) {
    int i = blockIdx.x * blockDim.x + threadIdx.x;
    if (i < E) {
        int d = dst[i];
        int pos = atomicAdd(&g_cur[d], 1);
        g_pes[pos] = make_int2(i, src[i]);
    }
}

// ---------------------------------------------------------------------------
__device__ __forceinline__ void load_w_rows(const float* __restrict__ W,
                                            int lane, ull* w0, ull* w1) {
    const ulonglong2* r0 = (const ulonglong2*)(W + (size_t)(2 * lane) * D);
    const ulonglong2* r1 = (const ulonglong2*)(W + (size_t)(2 * lane + 1) * D);
#pragma unroll
    for (int i = 0; i < 16; i++) {
        ulonglong2 v = r0[i]; w0[2 * i] = v.x; w0[2 * i + 1] = v.y;
        ulonglong2 u = r1[i]; w1[2 * i] = u.x; w1[2 * i + 1] = u.y;
    }
}

__device__ __forceinline__ float2 gemv2(const float* sRow, const ull* w0, const ull* w1) {
    const ulonglong2* xr = (const ulonglong2*)sRow;
    ull a00 = 0, a01 = 0, a10 = 0, a11 = 0;
#pragma unroll
    for (int i = 0; i < 16; i++) {
        ulonglong2 v = xr[i];
        a00 = fma2(v.x, w0[2 * i], a00);
        a10 = fma2(v.x, w1[2 * i], a10);
        a01 = fma2(v.y, w0[2 * i + 1], a01);
        a11 = fma2(v.y, w1[2 * i + 1], a11);
    }
    float2 f0 = unpack2(a00), f1 = unpack2(a01);
    float y0 = (f0.x + f1.x) + (f0.y + f1.y);
    f0 = unpack2(a10); f1 = unpack2(a11);
    float y1 = (f0.x + f1.x) + (f0.y + f1.y);
    return make_float2(y0, y1);
}

__device__ __forceinline__ void stage_rows(float* sXb, const float* __restrict__ G,
                                           size_t base, int nrows_total, int tid) {
#pragma unroll
    for (int i = 0; i < (WAVE * D / 4) / NT; i++) {
        int idx = tid + i * NT;
        size_t r = base + (idx >> 4);
        if (r < (size_t)nrows_total)
            cp16(sXb + (size_t)idx * 4, G + r * D + (size_t)(idx & 15) * 4);
    }
}

// ---------------------------------------------------------------------------
// g_h = node_h @ W_fc^T
__global__ __launch_bounds__(NT, 1) void k_node(
    const float* __restrict__ node_h, const float* __restrict__ W, int N) {
    extern __shared__ float smem[];
    float* sX = smem;
    int tid = threadIdx.x, lane = tid & 31, warp = tid >> 5;
    ull w0[32], w1[32];
    load_w_rows(W, lane, w0, w1);

    int nw = (N + WAVE - 1) / WAVE;
    int w = blockIdx.x;
    if (w >= nw) return;
    stage_rows(sX, node_h, (size_t)w * WAVE, N, tid);
    CP_COMMIT();

    int buf = 0;
    for (; w < nw; w += gridDim.x, buf ^= 1) {
        int wn = w + gridDim.x;
        if (wn < nw) {
            stage_rows(sX + (size_t)(buf ^ 1) * WAVE * D, node_h, (size_t)wn * WAVE, N, tid);
            CP_COMMIT();
            CP_WAIT1();
        } else {
            CP_WAIT0();
        }
        __syncthreads();
        int rbase = w * WAVE;
        const float* sXb = sX + (size_t)buf * WAVE * D;
#pragma unroll 1
        for (int r = warp; r < WAVE; r += NT / 32) {
            if (rbase + r >= N) break;
            float2 y = gemv2(sXb + (size_t)r * D, w0, w1);
            *(float2*)(g_h + (size_t)(rbase + r) * D + 2 * lane) = y;
        }
        __syncthreads();
    }
}

// ---------------------------------------------------------------------------
// Fused sorted edge pass + final output. One warp owns a contiguous node range.
// Dynamic smem layout (floats):
//   sLW  [0, D*LWS)                      transposed loop_W, padded
//   sX   [X0 + warp*RING*D ...]          edge row ring
//   sH   [H0 + warp*RING*D ...]          h[src] ring
//   sHn  [HN0 + warp*D ...]              h[n] staging for self-term
#define X0  (D * LWS)
#define H0  (X0 + ENW * RING * D)
#define HN0 (H0 + ENW * RING * D)
#define EDGE_SMEM_FLOATS (HN0 + ENW * D)

__global__ __launch_bounds__(ENT, 1) void k_edge2(
    const float* __restrict__ edge_h, const float* __restrict__ W,
    const float* __restrict__ loopW, float* __restrict__ out, int N) {
    extern __shared__ __align__(16) float smem[];
    float* sLW = smem;

    int tid = threadIdx.x, lane = tid & 31, warp = tid >> 5;
    float* sXw = smem + X0 + (size_t)warp * RING * D;
    float* sHw = smem + H0 + (size_t)warp * RING * D;
    float* sHn = smem + HN0 + (size_t)warp * D;

    for (int i = tid; i < D * D; i += ENT) {
        int k = i >> 6, j = i & 63;
        sLW[j * LWS + k] = loopW[i];
    }
    ull w0[32], w1[32];
    load_w_rows(W, lane, w0, w1);
    __syncthreads();

    int wpg = gridDim.x * ENW;
    int gw = blockIdx.x * ENW + warp;
    int npw = (N + wpg - 1) / wpg;
    int nbeg = gw * npw;
    if (nbeg >= N) return;
    int nend = nbeg + npw; if (nend > N) nend = N;

    int kbeg = g_off[nbeg];
    int kend_all = g_off[nend];
    int j0 = 2 * lane;

    int n = nbeg;
    int kendn = g_off[n + 1];
    float2 hn = *(const float2*)(g_h + (size_t)n * D + j0);
    float2 accN = make_float2(0.f, 0.f), accD = make_float2(0.f, 0.f);

    auto do_flush = [&](int node) {
        float v0, v1;
        if (accD.x > 0.f) {
            __syncwarp();
            *(float2*)(sHn + j0) = hn;
            __syncwarp();
            const ulonglong2* xr = (const ulonglong2*)sHn;
            const ulonglong2* u0 = (const ulonglong2*)(sLW + (size_t)j0 * LWS);
            const ulonglong2* u1 = (const ulonglong2*)(sLW + (size_t)(j0 + 1) * LWS);
            ull a0 = 0, a1 = 0, b0 = 0, b1 = 0;
#pragma unroll
            for (int i = 0; i < 16; i++) {
                ulonglong2 v = xr[i];
                ulonglong2 p = u0[i], q = u1[i];
                a0 = fma2(v.x, p.x, a0); a1 = fma2(v.y, p.y, a1);
                b0 = fma2(v.x, q.x, b0); b1 = fma2(v.y, q.y, b1);
            }
            float2 f0 = unpack2(a0), f1 = unpack2(a1);
            float gj0 = (f0.x + f1.x) + (f0.y + f1.y);
            f0 = unpack2(b0); f1 = unpack2(b1);
            float gj1 = (f0.x + f1.x) + (f0.y + f1.y);
            v0 = __fdividef(accN.x, accD.x) + gj0;
            v1 = __fdividef(accN.y, accD.y) + gj1;
        } else {
            v0 = hn.x; v1 = hn.y;
        }
        *(float2*)(out + (size_t)node * D + j0) =
            make_float2(fmaxf(v0, 0.f), fmaxf(v1, 0.f));
    };

    // pipeline prologue: LAD groups (one per future edge)
#pragma unroll
    for (int i = 0; i < LAD; i++) {
        if (kbeg + i < kend_all) {
            int2 p = g_pes[kbeg + i];
            int sl = (kbeg + i) & (RING - 1);
            cp8(sXw + sl * D + j0, edge_h + (size_t)p.x * D + j0);
            cp8(sHw + sl * D + j0, g_h + (size_t)p.y * D + j0);
        }
        CP_COMMIT();
    }
    int2 pes = (kbeg + LAD < kend_all) ? g_pes[kbeg + LAD] : make_int2(0, 0);

    for (int k = kbeg; k < kend_all; k++) {
        while (k == kendn) {           // node n's segment complete -> flush
            do_flush(n);
            n++;
            hn = *(const float2*)(g_h + (size_t)n * D + j0);
            accN = make_float2(0.f, 0.f); accD = make_float2(0.f, 0.f);
            kendn = g_off[n + 1];
        }
        if (k + LAD < kend_all) {
            int sl2 = (k + LAD) & (RING - 1);   // != k&(RING-1) since LAD < RING
            cp8(sXw + sl2 * D + j0, edge_h + (size_t)pes.x * D + j0);
            cp8(sHw + sl2 * D + j0, g_h + (size_t)pes.y * D + j0);
        }
        CP_COMMIT();
        if (k + LAD + 1 < kend_all) pes = g_pes[k + LAD + 1];
        CP_WAITLAD();        // <= LAD groups in flight; slot k&(RING-1) is safe
        __syncwarp();
        int slot = k & (RING - 1);
        float2 hv = *(const float2*)(sHw + slot * D + j0);
        float2 eh = gemv2(sXw + slot * D, w0, w1);
        float ex0 = __expf(eh.x), ex1 = __expf(eh.y);
        accD.x += ex0; accD.y += ex1;
        accN.x = fmaf(ex0, hv.x + eh.x, accN.x);
        accN.y = fmaf(ex1, hv.y + eh.y, accN.y);
    }
    // tail: flush current node, then remaining (empty) nodes
    for (;;) {
        do_flush(n);
        n++;
        if (n >= nend) break;
        hn = *(const float2*)(g_h + (size_t)n * D + j0);
        accN = make_float2(0.f, 0.f); accD = make_float2(0.f, 0.f);
    }
}

// ---------------------------------------------------------------------------
extern "C" void kernel_launch(void* const* d_in, const int* in_sizes, int n_in,
                              void* d_out, int out_size) {
    const float* node_h = (const float*)d_in[0];
    const float* edge_h = (const float*)d_in[1];
    const int*   src    = (const int*)d_in[2];
    const int*   dst    = (const int*)d_in[3];
    const float* W_fc   = (const float*)d_in[4];
    const float* W_fcr  = (const float*)d_in[5];
    const float* loop_W = (const float*)d_in[6];
    float* out = (float*)d_out;

    int N = in_sizes[0] / D;
    int E = in_sizes[2];
    if (N > MAXN) N = MAXN;
    if (E > MAXE) E = MAXE;

    const int ROW_SMEM  = 2 * WAVE * D * (int)sizeof(float);
    const int EDGE_SMEM = EDGE_SMEM_FLOATS * (int)sizeof(float);  // ~52 KB
    cudaFuncSetAttribute(k_node,  cudaFuncAttributeMaxDynamicSharedMemorySize, ROW_SMEM);
    cudaFuncSetAttribute(k_edge2, cudaFuncAttributeMaxDynamicSharedMemorySize, EDGE_SMEM);

    k_zero<<<((N + 3) / 4 + 255) / 256, 256>>>((N + 3) / 4);
    k_node<<<152, NT, ROW_SMEM>>>(node_h, W_fc, N);
    k_hist<<<(E + 255) / 256, 256>>>(dst, E);
    k_scan<<<1, 1024>>>(N, E);
    k_scatter<<<(E + 255) / 256, 256>>>(src, dst, E);
    k_edge2<<<152, ENT, EDGE_SMEM>>>(edge_h, W_fcr, loop_W, out, N);
}

// round 5
// speedup vs baseline: 1.4135x; 1.4135x over previous
#include <cuda_runtime.h>
#include <cstdint>

#define D 64
#define MAXN 100000
#define MAXE 1600000
#define WAVE 128
#define NT 256

#define ENT 256
#define ENW 8
#define EGRID 152
#define RING 8          // ring slots (power of 2)
#define LWS 68          // padded row stride for sLW
#define EOFFW 84        // per-warp offset-table entries (>= npw+1)

// Scratch (static device globals; no runtime allocation allowed)
__device__ float g_h[(size_t)MAXN * D];   // h = node_h @ W_fc^T
__device__ int   g_deg[MAXN];
__device__ int   g_off[MAXN + 1];
__device__ int   g_cur[MAXN];
__device__ int   g_bsum[128];
__device__ int2  g_pes[MAXE];             // permuted (edge_idx, src)

typedef unsigned long long ull;

__device__ __forceinline__ ull fma2(ull a, ull b, ull c) {
    ull d;
    asm("fma.rn.f32x2 %0, %1, %2, %3;" : "=l"(d) : "l"(a), "l"(b), "l"(c));
    return d;
}
__device__ __forceinline__ float2 unpack2(ull v) {
    float2 r;
    asm("mov.b64 {%0, %1}, %2;" : "=f"(r.x), "=f"(r.y) : "l"(v));
    return r;
}
__device__ __forceinline__ void cp16(void* s, const void* g) {
    unsigned a = (unsigned)__cvta_generic_to_shared(s);
    asm volatile("cp.async.cg.shared.global [%0], [%1], 16;" :: "r"(a), "l"(g));
}
__device__ __forceinline__ void cp8(void* s, const void* g) {
    unsigned a = (unsigned)__cvta_generic_to_shared(s);
    asm volatile("cp.async.ca.shared.global [%0], [%1], 8;" :: "r"(a), "l"(g));
}
#define CP_COMMIT() asm volatile("cp.async.commit_group;" ::: "memory")
#define CP_WAIT1()  asm volatile("cp.async.wait_group 1;" ::: "memory")
#define CP_WAIT0()  asm volatile("cp.async.wait_group 0;" ::: "memory")
#define CP_WAIT3()  asm volatile("cp.async.wait_group 3;" ::: "memory")

// ---------------------------------------------------------------------------
__global__ void k_zero(int n4) {  // zero g_deg; n4 = ceil(N/4)
    int i = blockIdx.x * blockDim.x + threadIdx.x;
    if (i < n4) ((int4*)g_deg)[i] = make_int4(0, 0, 0, 0);
}

__global__ void k_hist(const int* __restrict__ dst, int E) {
    int i = blockIdx.x * blockDim.x + threadIdx.x;
    if (i < E) atomicAdd(&g_deg[dst[i]], 1);
}

// -- parallel scan: block exclusive scan + block sums --
__global__ void k_scan1(int N) {
    __shared__ int s[1024];
    int t = threadIdx.x;
    int i = blockIdx.x * 1024 + t;
    int v = (i < N) ? g_deg[i] : 0;
    s[t] = v; __syncthreads();
#pragma unroll
    for (int d = 1; d < 1024; d <<= 1) {
        int u = (t >= d) ? s[t - d] : 0;
        __syncthreads();
        s[t] += u;
        __syncthreads();
    }
    if (i < N) g_off[i] = s[t] - v;            // local exclusive
    if (t == 1023) g_bsum[blockIdx.x] = s[t];  // block total
}

// scan the (<=128) block sums; write grand total to g_off[N]
__global__ void k_scan2(int nb, int N) {
    __shared__ int s[128];
    int t = threadIdx.x;
    int v = (t < nb) ? g_bsum[t] : 0;
    s[t] = v; __syncthreads();
#pragma unroll
    for (int d = 1; d < 128; d <<= 1) {
        int u = (t >= d) ? s[t - d] : 0;
        __syncthreads();
        s[t] += u;
        __syncthreads();
    }
    if (t < nb) g_bsum[t] = s[t] - v;
    if (t == 127) g_off[N] = s[127];
}

__global__ void k_scan3(int N) {
    int i = blockIdx.x * 1024 + threadIdx.x;
    if (i < N) {
        int o = g_off[i] + g_bsum[blockIdx.x];
        g_off[i] = o;
        g_cur[i] = o;
    }
}

__global__ void k_scatter(const int* __restrict__ src, const int* __restrict__ dst, int E) {
    int i = blockIdx.x * blockDim.x + threadIdx.x;
    if (i < E) {
        int d = dst[i];
        int pos = atomicAdd(&g_cur[d], 1);
        g_pes[pos] = make_int2(i, src[i]);
    }
}

// ---------------------------------------------------------------------------
__device__ __forceinline__ void load_w_rows(const float* __restrict__ W,
                                            int lane, ull* w0, ull* w1) {
    const ulonglong2* r0 = (const ulonglong2*)(W + (size_t)(2 * lane) * D);
    const ulonglong2* r1 = (const ulonglong2*)(W + (size_t)(2 * lane + 1) * D);
#pragma unroll
    for (int i = 0; i < 16; i++) {
        ulonglong2 v = r0[i]; w0[2 * i] = v.x; w0[2 * i + 1] = v.y;
        ulonglong2 u = r1[i]; w1[2 * i] = u.x; w1[2 * i + 1] = u.y;
    }
}

__device__ __forceinline__ float2 gemv2(const float* sRow, const ull* w0, const ull* w1) {
    const ulonglong2* xr = (const ulonglong2*)sRow;
    ull a00 = 0, a01 = 0, a10 = 0, a11 = 0;
#pragma unroll
    for (int i = 0; i < 16; i++) {
        ulonglong2 v = xr[i];
        a00 = fma2(v.x, w0[2 * i], a00);
        a10 = fma2(v.x, w1[2 * i], a10);
        a01 = fma2(v.y, w0[2 * i + 1], a01);
        a11 = fma2(v.y, w1[2 * i + 1], a11);
    }
    float2 f0 = unpack2(a00), f1 = unpack2(a01);
    float y0 = (f0.x + f1.x) + (f0.y + f1.y);
    f0 = unpack2(a10); f1 = unpack2(a11);
    float y1 = (f0.x + f1.x) + (f0.y + f1.y);
    return make_float2(y0, y1);
}

__device__ __forceinline__ void stage_rows(float* sXb, const float* __restrict__ G,
                                           size_t base, int nrows_total, int tid) {
#pragma unroll
    for (int i = 0; i < (WAVE * D / 4) / NT; i++) {
        int idx = tid + i * NT;
        size_t r = base + (idx >> 4);
        if (r < (size_t)nrows_total)
            cp16(sXb + (size_t)idx * 4, G + r * D + (size_t)(idx & 15) * 4);
    }
}

// ---------------------------------------------------------------------------
// g_h = node_h @ W_fc^T
__global__ __launch_bounds__(NT, 1) void k_node(
    const float* __restrict__ node_h, const float* __restrict__ W, int N) {
    extern __shared__ float smem[];
    float* sX = smem;
    int tid = threadIdx.x, lane = tid & 31, warp = tid >> 5;
    ull w0[32], w1[32];
    load_w_rows(W, lane, w0, w1);

    int nw = (N + WAVE - 1) / WAVE;
    int w = blockIdx.x;
    if (w >= nw) return;
    stage_rows(sX, node_h, (size_t)w * WAVE, N, tid);
    CP_COMMIT();

    int buf = 0;
    for (; w < nw; w += gridDim.x, buf ^= 1) {
        int wn = w + gridDim.x;
        if (wn < nw) {
            stage_rows(sX + (size_t)(buf ^ 1) * WAVE * D, node_h, (size_t)wn * WAVE, N, tid);
            CP_COMMIT();
            CP_WAIT1();
        } else {
            CP_WAIT0();
        }
        __syncthreads();
        int rbase = w * WAVE;
        const float* sXb = sX + (size_t)buf * WAVE * D;
#pragma unroll 1
        for (int r = warp; r < WAVE; r += NT / 32) {
            if (rbase + r >= N) break;
            float2 y = gemv2(sXb + (size_t)r * D, w0, w1);
            *(float2*)(g_h + (size_t)(rbase + r) * D + 2 * lane) = y;
        }
        __syncthreads();
    }
}

// ---------------------------------------------------------------------------
// Fused sorted edge pass + final output. One warp owns a contiguous node range.
// Dynamic smem layout (float units):
#define X0   (D * LWS)
#define H0   (X0 + ENW * RING * D)
#define HN0  (H0 + ENW * RING * D)
#define OFF0 (HN0 + ENW * D)
#define EDGE_SMEM_FLOATS (OFF0 + ENW * EOFFW)

__global__ __launch_bounds__(ENT, 1) void k_edge2(
    const float* __restrict__ edge_h, const float* __restrict__ W,
    const float* __restrict__ loopW, float* __restrict__ out, int N) {
    extern __shared__ __align__(16) float smem[];
    float* sLW = smem;

    int tid = threadIdx.x, lane = tid & 31, warp = tid >> 5;
    float* sXw = smem + X0 + (size_t)warp * RING * D;
    float* sHw = smem + H0 + (size_t)warp * RING * D;
    float* sHn = smem + HN0 + (size_t)warp * D;
    int*   sOf = (int*)(smem + OFF0) + (size_t)warp * EOFFW;

    for (int i = tid; i < D * D; i += ENT) {
        int k = i >> 6, j = i & 63;
        sLW[j * LWS + k] = loopW[i];
    }
    ull w0[32], w1[32];
    load_w_rows(W, lane, w0, w1);
    __syncthreads();

    int wpg = gridDim.x * ENW;
    int gw = blockIdx.x * ENW + warp;
    int npw = (N + wpg - 1) / wpg;
    int nbeg = gw * npw;
    if (nbeg >= N) return;
    int nend = nbeg + npw; if (nend > N) nend = N;
    int nloc = nend - nbeg;                   // <= EOFFW-1

    // preload this warp's offset table into smem
    for (int i = lane; i <= nloc; i += 32) sOf[i] = g_off[nbeg + i];
    __syncwarp();

    int kbeg = sOf[0];
    int kend_all = sOf[nloc];
    int j0 = 2 * lane;

    int n = nbeg;
    int kendn = sOf[1];
    float2 hn = *(const float2*)(g_h + (size_t)n * D + j0);
    float2 accN = make_float2(0.f, 0.f), accD = make_float2(0.f, 0.f);

    auto do_flush = [&](int node) {
        float v0, v1;
        if (accD.x > 0.f) {
            __syncwarp();
            *(float2*)(sHn + j0) = hn;
            __syncwarp();
            const ulonglong2* xr = (const ulonglong2*)sHn;
            const ulonglong2* u0 = (const ulonglong2*)(sLW + (size_t)j0 * LWS);
            const ulonglong2* u1 = (const ulonglong2*)(sLW + (size_t)(j0 + 1) * LWS);
            ull a0 = 0, a1 = 0, b0 = 0, b1 = 0;
#pragma unroll
            for (int i = 0; i < 16; i++) {
                ulonglong2 v = xr[i];
                ulonglong2 p = u0[i], q = u1[i];
                a0 = fma2(v.x, p.x, a0); a1 = fma2(v.y, p.y, a1);
                b0 = fma2(v.x, q.x, b0); b1 = fma2(v.y, q.y, b1);
            }
            float2 f0 = unpack2(a0), f1 = unpack2(a1);
            float gj0 = (f0.x + f1.x) + (f0.y + f1.y);
            f0 = unpack2(b0); f1 = unpack2(b1);
            float gj1 = (f0.x + f1.x) + (f0.y + f1.y);
            v0 = __fdividef(accN.x, accD.x) + gj0;
            v1 = __fdividef(accN.y, accD.y) + gj1;
        } else {
            v0 = hn.x; v1 = hn.y;
        }
        *(float2*)(out + (size_t)node * D + j0) =
            make_float2(fmaxf(v0, 0.f), fmaxf(v1, 0.f));
    };

    auto consume = [&](int k) {
        while (k == kendn) {           // node n's segment complete -> flush
            do_flush(n);
            n++;
            hn = *(const float2*)(g_h + (size_t)n * D + j0);
            accN = make_float2(0.f, 0.f); accD = make_float2(0.f, 0.f);
            kendn = sOf[n - nbeg + 1];
        }
        int slot = k & (RING - 1);
        float2 hv = *(const float2*)(sHw + slot * D + j0);
        float2 eh = gemv2(sXw + slot * D, w0, w1);
        float ex0 = __expf(eh.x), ex1 = __expf(eh.y);
        accD.x += ex0; accD.y += ex1;
        accN.x = fmaf(ex0, hv.x + eh.x, accN.x);
        accN.y = fmaf(ex1, hv.y + eh.y, accN.y);
    };

    // pipeline prologue: 3 pair-groups covering edges kbeg .. kbeg+5
#pragma unroll
    for (int g = 0; g < 3; g++) {
#pragma unroll
        for (int h = 0; h < 2; h++) {
            int e = kbeg + 2 * g + h;
            if (e < kend_all) {
                int2 p = g_pes[e];
                int sl = e & (RING - 1);
                cp8(sXw + sl * D + j0, edge_h + (size_t)p.x * D + j0);
                cp8(sHw + sl * D + j0, g_h + (size_t)p.y * D + j0);
            }
        }
        CP_COMMIT();
    }
    int2 pa = make_int2(0, 0), pb = make_int2(0, 0);
    if (kbeg + 6 < kend_all) pa = g_pes[kbeg + 6];
    if (kbeg + 7 < kend_all) pb = g_pes[kbeg + 7];

    for (int k = kbeg; k < kend_all; k += 2) {
        // issue prefetch for edges k+6, k+7 (addresses were fetched last iter)
        if (k + 6 < kend_all) {
            int sl = (k + 6) & (RING - 1);
            cp8(sXw + sl * D + j0, edge_h + (size_t)pa.x * D + j0);
            cp8(sHw + sl * D + j0, g_h + (size_t)pa.y * D + j0);
        }
        if (k + 7 < kend_all) {
            int sl = (k + 7) & (RING - 1);
            cp8(sXw + sl * D + j0, edge_h + (size_t)pb.x * D + j0);
            cp8(sHw + sl * D + j0, g_h + (size_t)pb.y * D + j0);
        }
        CP_COMMIT();
        // fetch pes for next iteration's prefetch (edges k+8, k+9)
        if (k + 8 < kend_all) pa = g_pes[k + 8];
        if (k + 9 < kend_all) pb = g_pes[k + 9];
        CP_WAIT3();        // oldest pending group (edges k,k+1) completes
        __syncwarp();
        consume(k);
        if (k + 1 < kend_all) consume(k + 1);
    }
    // tail: flush current node, then remaining (empty) nodes
    for (;;) {
        do_flush(n);
        n++;
        if (n >= nend) break;
        hn = *(const float2*)(g_h + (size_t)n * D + j0);
        accN = make_float2(0.f, 0.f); accD = make_float2(0.f, 0.f);
    }
}

// ---------------------------------------------------------------------------
extern "C" void kernel_launch(void* const* d_in, const int* in_sizes, int n_in,
                              void* d_out, int out_size) {
    const float* node_h = (const float*)d_in[0];
    const float* edge_h = (const float*)d_in[1];
    const int*   src    = (const int*)d_in[2];
    const int*   dst    = (const int*)d_in[3];
    const float* W_fc   = (const float*)d_in[4];
    const float* W_fcr  = (const float*)d_in[5];
    const float* loop_W = (const float*)d_in[6];
    float* out = (float*)d_out;

    int N = in_sizes[0] / D;
    int E = in_sizes[2];
    if (N > MAXN) N = MAXN;
    if (E > MAXE) E = MAXE;

    const int ROW_SMEM  = 2 * WAVE * D * (int)sizeof(float);
    const int EDGE_SMEM = EDGE_SMEM_FLOATS * (int)sizeof(float);  // ~55 KB
    cudaFuncSetAttribute(k_node,  cudaFuncAttributeMaxDynamicSharedMemorySize, ROW_SMEM);
    cudaFuncSetAttribute(k_edge2, cudaFuncAttributeMaxDynamicSharedMemorySize, EDGE_SMEM);

    int nb = (N + 1023) / 1024;   // <= 98 for N <= 100000
    k_zero<<<((N + 3) / 4 + 255) / 256, 256>>>((N + 3) / 4);
    k_node<<<152, NT, ROW_SMEM>>>(node_h, W_fc, N);
    k_hist<<<(E + 255) / 256, 256>>>(dst, E);
    k_scan1<<<nb, 1024>>>(N);
    k_scan2<<<1, 128>>>(nb, N);
    k_scan3<<<nb, 1024>>>(N);
    k_scatter<<<(E + 255) / 256, 256>>>(src, dst, E);
    k_edge2<<<EGRID, ENT, EDGE_SMEM>>>(edge_h, W_fcr, loop_W, out, N);
}